// round 10
// baseline (speedup 1.0000x reference)
#include <cuda_runtime.h>
#include <cuda_bf16.h>
#include <cstdint>

#define DIM 256
#define NMOD 5
#define NROWS 16384
#define XPITCH (NMOD * DIM)

#define APITCH 264            // A_s pitch (bf16)
#define BPITCH 72             // B pitch (bf16), 64 K-cols + 8 pad
#define CHUNK_BYTES (256 * BPITCH * 2)   // 36864
#define CHUNK_U16   (CHUNK_BYTES / 16)   // 2304

// Fused per-branch matrices, PRE-PADDED image: chunk c = n*4+kc holds
// [256 N-rows][72 cols (64 K + 8 pad)] bf16 -> contiguous cp.async.
__device__ __align__(16) __nv_bfloat16 g_M[NMOD * 4][256][BPITCH];
__device__ float g_c[NMOD][DIM];
// branch outputs workspace (fp32)
__device__ __align__(16) float g_a[NMOD][NROWS][DIM];

// ---------------- helpers ----------------
__device__ __forceinline__ void ldsm_x4(uint32_t* r, const void* p) {
    uint32_t addr = (uint32_t)__cvta_generic_to_shared(p);
    asm volatile("ldmatrix.sync.aligned.m8n8.x4.shared.b16 {%0,%1,%2,%3}, [%4];"
                 : "=r"(r[0]), "=r"(r[1]), "=r"(r[2]), "=r"(r[3]) : "r"(addr));
}
__device__ __forceinline__ void mma16816(float* d, const uint32_t* a, const uint32_t* b) {
    asm volatile("mma.sync.aligned.m16n8k16.row.col.f32.bf16.bf16.f32 "
                 "{%0,%1,%2,%3},{%4,%5,%6,%7},{%8,%9},{%0,%1,%2,%3};"
                 : "+f"(d[0]), "+f"(d[1]), "+f"(d[2]), "+f"(d[3])
                 : "r"(a[0]), "r"(a[1]), "r"(a[2]), "r"(a[3]), "r"(b[0]), "r"(b[1]));
}
__device__ __forceinline__ float warp_sum(float v) {
#pragma unroll
    for (int o = 16; o; o >>= 1) v += __shfl_xor_sync(0xffffffffu, v, o);
    return v;
}
__device__ __forceinline__ void cp_async16(void* smem, const void* g) {
    uint32_t s = (uint32_t)__cvta_generic_to_shared(smem);
    asm volatile("cp.async.cg.shared.global [%0], [%1], 16;\n" :: "r"(s), "l"(g));
}
__device__ __forceinline__ void cp_commit() { asm volatile("cp.async.commit_group;\n"); }
__device__ __forceinline__ void cp_wait0() { asm volatile("cp.async.wait_group 0;\n"); }

// ------------------------------------------------------------------
// prologue: M_n = Wo_n @ Wv_n (bf16 mma) -> padded image; c_n bias.
// grid (8, 5): bx = 32-row d-block, by = n.  256 threads, warp tile 16x64.
// ------------------------------------------------------------------
__global__ __launch_bounds__(256, 1)
void fuse_weights_kernel(const float* __restrict__ sWi, const float* __restrict__ sbi,
                         const float* __restrict__ sWo, const float* __restrict__ sbo,
                         const float* __restrict__ cWi, const float* __restrict__ cbi,
                         const float* __restrict__ cWo, const float* __restrict__ cbo) {
    extern __shared__ char sm[];
    __nv_bfloat16* A_s = (__nv_bfloat16*)sm;                 // [32][APITCH]
    __nv_bfloat16* B_s = (__nv_bfloat16*)(sm + 16896);       // [256][BPITCH]
    float* bv_s = (float*)(sm + 16896 + 36864);
    float* bred = (float*)B_s;

    const int n = blockIdx.y, bx = blockIdx.x;
    const float* Wo = (n == 0) ? sWo : cWo + (size_t)(n - 1) * DIM * DIM;
    const float* Wv = (n == 0) ? sWi + 2 * DIM * DIM
                               : cWi + (size_t)(n - 1) * 3 * DIM * DIM + 2 * DIM * DIM;
    const float* bv = (n == 0) ? sbi + 2 * DIM : cbi + (size_t)(n - 1) * 3 * DIM + 2 * DIM;
    const float* bo = (n == 0) ? sbo : cbo + (size_t)(n - 1) * DIM;

    const int tid = threadIdx.x;
    const int w = tid >> 5, l = tid & 31;
    const int wm = w & 1, wn = w >> 1;
    const int lq = l >> 2, lr = l & 3;

    bv_s[tid] = bv[tid];
#pragma unroll
    for (int i = 0; i < 8; i++) {
        int e = tid + i * 256, r = e >> 6, c4 = (e & 63) << 2;
        float4 v = *(const float4*)(Wo + (size_t)(bx * 32 + r) * DIM + c4);
        __nv_bfloat16* dst = A_s + r * APITCH + c4;
        *(__nv_bfloat162*)(dst)     = __floats2bfloat162_rn(v.x, v.y);
        *(__nv_bfloat162*)(dst + 2) = __floats2bfloat162_rn(v.z, v.w);
    }

    float cf[8][4];
#pragma unroll
    for (int nt = 0; nt < 8; nt++)
#pragma unroll
        for (int i = 0; i < 4; i++) cf[nt][i] = 0.f;

#pragma unroll 1
    for (int kc = 0; kc < 4; kc++) {
        __syncthreads();
        int jc = kc * 64;
#pragma unroll
        for (int i = 0; i < 16; i++) {
            int e = tid + i * 256;
            int k = e & 255, j4 = (e >> 8) << 2;
            float v0 = Wv[(size_t)(jc + j4 + 0) * DIM + k];
            float v1 = Wv[(size_t)(jc + j4 + 1) * DIM + k];
            float v2 = Wv[(size_t)(jc + j4 + 2) * DIM + k];
            float v3 = Wv[(size_t)(jc + j4 + 3) * DIM + k];
            __nv_bfloat16* dst = B_s + k * BPITCH + j4;
            *(__nv_bfloat162*)(dst)     = __floats2bfloat162_rn(v0, v1);
            *(__nv_bfloat162*)(dst + 2) = __floats2bfloat162_rn(v2, v3);
        }
        __syncthreads();
#pragma unroll
        for (int ks = 0; ks < 4; ks++) {
            uint32_t af[4];
            {
                int row = wm * 16 + (l & 7) + ((l >> 3) & 1) * 8;
                int col = kc * 64 + ks * 16 + (l >> 4) * 8;
                ldsm_x4(af, A_s + row * APITCH + col);
            }
            uint32_t bfr[8][2];
#pragma unroll
            for (int np = 0; np < 4; np++) {
                int row = wn * 64 + np * 16 + (l & 7) + (l >> 4) * 8;
                int col = ks * 16 + ((l >> 3) & 1) * 8;
                uint32_t r4[4];
                ldsm_x4(r4, B_s + row * BPITCH + col);
                bfr[2 * np][0] = r4[0]; bfr[2 * np][1] = r4[1];
                bfr[2 * np + 1][0] = r4[2]; bfr[2 * np + 1][1] = r4[3];
            }
#pragma unroll
            for (int nt = 0; nt < 8; nt++)
                mma16816(cf[nt], af, bfr[nt]);
        }
    }
    __syncthreads();

    // store to padded image: chunk = n*4 + (k>>6), row = d, col = k&63
#pragma unroll
    for (int nt = 0; nt < 8; nt++) {
        int d = bx * 32 + wm * 16 + lq;
        int k = wn * 64 + nt * 8 + 2 * lr;
        int ch = n * 4 + (k >> 6);
        int col = k & 63;
        *(__nv_bfloat162*)&g_M[ch][d][col]     = __floats2bfloat162_rn(cf[nt][0], cf[nt][1]);
        *(__nv_bfloat162*)&g_M[ch][d + 8][col] = __floats2bfloat162_rn(cf[nt][2], cf[nt][3]);
    }

    // bias: c[d] = Wo[d,:] @ bv + bo[d]
    {
        int row = tid & 31, part = tid >> 5;
        float s = 0.f;
#pragma unroll 8
        for (int j = 0; j < 32; j++) {
            int jj = part * 32 + j;
            s += __bfloat162float(A_s[row * APITCH + jj]) * bv_s[jj];
        }
        bred[part * 32 + row] = s;
        __syncthreads();
        if (tid < 32) {
            float c = bo[bx * 32 + tid];
#pragma unroll
            for (int p = 0; p < 8; p++) c += bred[p * 32 + tid];
            g_c[n][bx * 32 + tid] = c;
        }
    }
}

// ------------------------------------------------------------------
// GEMM kernel: a_n = X_mod(n) @ M_n^T.  grid (256, 5): bx = 64-row tile,
// by = branch.  256 threads (8 warps, 2Mx4N, warp tile 32x64), 2 CTAs/SM.
// ------------------------------------------------------------------
constexpr int GSM_A = 0;                         // 64*264*2 = 33792
constexpr int GSM_B = 33792;                     // 2 * 36864 = 73728
constexpr int GSM_TOTAL = GSM_B + 2 * CHUNK_BYTES;  // 107520

__global__ __launch_bounds__(256, 2)
void gemm_kernel(const float* __restrict__ x, const int* __restrict__ modal_idx) {
    extern __shared__ char sm[];
    __nv_bfloat16* A_s = (__nv_bfloat16*)(sm + GSM_A);
    char* B_s = sm + GSM_B;

    const int n = blockIdx.y;
    const int r0 = blockIdx.x * 64;
    const int mi = *modal_idx;
    const int mod = (n == 0) ? mi : (((n - 1) < mi) ? (n - 1) : n);

    const int tid = threadIdx.x;
    const int w = tid >> 5, l = tid & 31;
    const int wm = w & 1, wn = w >> 1;
    const int lq = l >> 2, lr = l & 3;

    // prefetch B chunk n*4 -> buf0 (contiguous)
    {
        const char* src = (const char*)g_M + (size_t)(n * 4) * CHUNK_BYTES;
#pragma unroll
        for (int i = 0; i < 9; i++) {
            int e = tid + i * 256;
            if (e < CHUNK_U16) cp_async16(B_s + e * 16, src + e * 16);
        }
        cp_commit();
    }

    // A tile: x rows r0..r0+63, modality mod -> bf16
#pragma unroll
    for (int i = 0; i < 16; i++) {
        int e = tid + i * 256, r = e >> 6, c4 = (e & 63) << 2;
        float4 v = *(const float4*)(x + (size_t)(r0 + r) * XPITCH + mod * DIM + c4);
        __nv_bfloat16* dst = A_s + r * APITCH + c4;
        *(__nv_bfloat162*)(dst)     = __floats2bfloat162_rn(v.x, v.y);
        *(__nv_bfloat162*)(dst + 2) = __floats2bfloat162_rn(v.z, v.w);
    }

    float cf[2][8][4];
#pragma unroll
    for (int mt = 0; mt < 2; mt++)
#pragma unroll
        for (int nt = 0; nt < 8; nt++)
#pragma unroll
            for (int i = 0; i < 4; i++) cf[mt][nt][i] = 0.f;

#pragma unroll 1
    for (int kc = 0; kc < 4; kc++) {
        cp_wait0();
        __syncthreads();   // chunk kc visible; A_s visible (kc==0); other buf free
        if (kc < 3) {
            const char* src = (const char*)g_M + (size_t)(n * 4 + kc + 1) * CHUNK_BYTES;
            char* dst = B_s + ((kc + 1) & 1) * CHUNK_BYTES;
#pragma unroll
            for (int i = 0; i < 9; i++) {
                int e = tid + i * 256;
                if (e < CHUNK_U16) cp_async16(dst + e * 16, src + e * 16);
            }
            cp_commit();
        }
        const __nv_bfloat16* Bc = (const __nv_bfloat16*)(B_s + (kc & 1) * CHUNK_BYTES);
#pragma unroll
        for (int ks = 0; ks < 4; ks++) {
            uint32_t af[2][4];
#pragma unroll
            for (int mt = 0; mt < 2; mt++) {
                int row = wm * 32 + mt * 16 + (l & 7) + ((l >> 3) & 1) * 8;
                int col = kc * 64 + ks * 16 + (l >> 4) * 8;
                ldsm_x4(af[mt], A_s + row * APITCH + col);
            }
            uint32_t bfr[8][2];
#pragma unroll
            for (int np = 0; np < 4; np++) {
                int row = wn * 64 + np * 16 + (l & 7) + (l >> 4) * 8;
                int col = ks * 16 + ((l >> 3) & 1) * 8;
                uint32_t r4[4];
                ldsm_x4(r4, Bc + row * BPITCH + col);
                bfr[2 * np][0] = r4[0]; bfr[2 * np][1] = r4[1];
                bfr[2 * np + 1][0] = r4[2]; bfr[2 * np + 1][1] = r4[3];
            }
#pragma unroll
            for (int mt = 0; mt < 2; mt++)
#pragma unroll
                for (int nt = 0; nt < 8; nt++)
                    mma16816(cf[mt][nt], af[mt], bfr[nt]);
        }
    }

    // store fragments (fp32)
#pragma unroll
    for (int mt = 0; mt < 2; mt++)
#pragma unroll
        for (int nt = 0; nt < 8; nt++) {
            int row = wm * 32 + mt * 16 + lq;
            int col = wn * 64 + nt * 8 + 2 * lr;
            *(float2*)&g_a[n][r0 + row][col]     = make_float2(cf[mt][nt][0], cf[mt][nt][1]);
            *(float2*)&g_a[n][r0 + row + 8][col] = make_float2(cf[mt][nt][2], cf[mt][nt][3]);
        }
}

// ------------------------------------------------------------------
// epilogue kernel: gates + gated LN combine + final LN.  grid 512 (32 rows),
// 256 threads (8 warps, 4 rows/warp). Pure streaming, register-resident rows.
// ------------------------------------------------------------------
__global__ __launch_bounds__(256)
void epilogue_kernel(const float* __restrict__ x,
                     const float* __restrict__ cross_ln_g, const float* __restrict__ cross_ln_b,
                     const float* __restrict__ gate_ln_g, const float* __restrict__ gate_ln_b,
                     const float* __restrict__ gate_W, const float* __restrict__ gate_b,
                     const float* __restrict__ final_ln_g, const float* __restrict__ final_ln_b,
                     const int* __restrict__ modal_idx, float* __restrict__ out) {
    __shared__ float gw_s[1792];   // gate_W 1280 | gate_ln_g 256 | gate_ln_b 256

    const int tid = threadIdx.x;
    const int w = tid >> 5, l = tid & 31;
    const int mi = *modal_idx;

    for (int i = tid; i < 1792; i += 256)
        gw_s[i] = (i < 1280) ? gate_W[i] : (i < 1536 ? gate_ln_g[i - 1280] : gate_ln_b[i - 1536]);
    float gb[5];
#pragma unroll
    for (int n = 0; n < 5; n++) gb[n] = gate_b[n];
    __syncthreads();

#pragma unroll 1
    for (int ri = 0; ri < 4; ri++) {
        const int r = blockIdx.x * 32 + w * 4 + ri;
        const float* qr = x + (size_t)r * XPITCH + mi * DIM;

        float q[8];
        float sum = 0.f, sq = 0.f;
#pragma unroll
        for (int j = 0; j < 8; j++) {
            q[j] = qr[l + 32 * j];
            sum += q[j]; sq += q[j] * q[j];
        }
        sum = warp_sum(sum); sq = warp_sum(sq);
        float m = sum * (1.f / DIM);
        float rs = rsqrtf(fmaxf(sq * (1.f / DIM) - m * m, 0.f) + 1e-5f);

        // gates
        float g[5];
        {
            float lnv[8];
#pragma unroll
            for (int j = 0; j < 8; j++) {
                int c = l + 32 * j;
                lnv[j] = (q[j] - m) * rs * gw_s[1280 + c] + gw_s[1536 + c];
            }
#pragma unroll
            for (int n = 0; n < 5; n++) {
                float s = 0.f;
#pragma unroll
                for (int j = 0; j < 8; j++) s += lnv[j] * gw_s[n * DIM + l + 32 * j];
                g[n] = warp_sum(s) + gb[n];
            }
            float mx = g[0];
#pragma unroll
            for (int n = 1; n < 5; n++) mx = fmaxf(mx, g[n]);
            float es = 0.f;
#pragma unroll
            for (int n = 0; n < 5; n++) { g[n] = expf(g[n] - mx); es += g[n]; }
            float inv = 1.f / es;
#pragma unroll
            for (int n = 0; n < 5; n++) g[n] *= inv;
        }

        // acc = g0 * (a0 + c0)
        float acc[8];
#pragma unroll
        for (int j = 0; j < 8; j++) {
            int c = l + 32 * j;
            acc[j] = g[0] * (g_a[0][r][c] + g_c[0][c]);
        }

        // cross branches
#pragma unroll 1
        for (int n = 1; n < 5; n++) {
            float t[8], s = 0.f, ss = 0.f;
#pragma unroll
            for (int j = 0; j < 8; j++) {
                int c = l + 32 * j;
                t[j] = q[j] + g_a[n][r][c] + g_c[n][c];
                s += t[j]; ss += t[j] * t[j];
            }
            s = warp_sum(s); ss = warp_sum(ss);
            float mn = s * (1.f / DIM);
            float rn = rsqrtf(fmaxf(ss * (1.f / DIM) - mn * mn, 0.f) + 1e-5f);
            const float* gam = cross_ln_g + (n - 1) * DIM;
            const float* bet = cross_ln_b + (n - 1) * DIM;
#pragma unroll
            for (int j = 0; j < 8; j++) {
                int c = l + 32 * j;
                acc[j] += g[n] * ((t[j] - mn) * rn * gam[c] + bet[c]);
            }
        }

        // final LN(q + acc)
        float s = 0.f, ss = 0.f;
#pragma unroll
        for (int j = 0; j < 8; j++) {
            acc[j] += q[j];
            s += acc[j]; ss += acc[j] * acc[j];
        }
        s = warp_sum(s); ss = warp_sum(ss);
        float mf = s * (1.f / DIM);
        float rf = rsqrtf(fmaxf(ss * (1.f / DIM) - mf * mf, 0.f) + 1e-5f);
        float* orow = out + (size_t)r * DIM;
#pragma unroll
        for (int j = 0; j < 8; j++) {
            int c = l + 32 * j;
            orow[c] = (acc[j] - mf) * rf * final_ln_g[c] + final_ln_b[c];
        }
    }
}

// ------------------------------------------------------------------
extern "C" void kernel_launch(void* const* d_in, const int* in_sizes, int n_in,
                              void* d_out, int out_size) {
    (void)in_sizes; (void)n_in; (void)out_size;
    const float* x          = (const float*)d_in[0];
    const float* self_Wi    = (const float*)d_in[1];
    const float* self_bi    = (const float*)d_in[2];
    const float* self_Wo    = (const float*)d_in[3];
    const float* self_bo    = (const float*)d_in[4];
    const float* cross_Wi   = (const float*)d_in[5];
    const float* cross_bi   = (const float*)d_in[6];
    const float* cross_Wo   = (const float*)d_in[7];
    const float* cross_bo   = (const float*)d_in[8];
    const float* cross_ln_g = (const float*)d_in[9];
    const float* cross_ln_b = (const float*)d_in[10];
    const float* gate_ln_g  = (const float*)d_in[11];
    const float* gate_ln_b  = (const float*)d_in[12];
    const float* gate_W     = (const float*)d_in[13];
    const float* gate_b     = (const float*)d_in[14];
    const float* final_ln_g = (const float*)d_in[15];
    const float* final_ln_b = (const float*)d_in[16];
    const int*   modal_idx  = (const int*)d_in[17];
    float* out = (float*)d_out;

    static bool attr_set = false;
    if (!attr_set) {
        cudaFuncSetAttribute(fuse_weights_kernel,
                             cudaFuncAttributeMaxDynamicSharedMemorySize, 54784);
        cudaFuncSetAttribute(gemm_kernel,
                             cudaFuncAttributeMaxDynamicSharedMemorySize, GSM_TOTAL);
        attr_set = true;
    }

    fuse_weights_kernel<<<dim3(8, 5), 256, 54784>>>(self_Wi, self_bi, self_Wo, self_bo,
                                                    cross_Wi, cross_bi, cross_Wo, cross_bo);
    gemm_kernel<<<dim3(256, 5), 256, GSM_TOTAL>>>(x, modal_idx);
    epilogue_kernel<<<512, 256>>>(x, cross_ln_g, cross_ln_b, gate_ln_g, gate_ln_b,
                                  gate_W, gate_b, final_ln_g, final_ln_b, modal_idx, out);
}